// round 12
// baseline (speedup 1.0000x reference)
#include <cuda_runtime.h>
#include <cstdint>

#define BB 64
#define NN 500
#define CC 128
#define HH 256
#define GRIDN 128
#define GRIDB 8          // blocks that run the MLP phase
#define THREADS 1024
#define XS_STRIDE 264    // 256 + 8 pad

// band thresholds squared (0.19^2, 0.21^2)
#define LO2 0.0361f
#define HI2 0.0441f

// MLP activation ping-pong + grid-barrier state
__device__ __align__(16) float g_act[2][BB * HH];
__device__ unsigned g_count[8];
__device__ volatile unsigned g_sense[8];

// R5/R8 barrier (measured fastest): all threads fence, thread 0 signals/spins.
// target = number of participating blocks.
__device__ __forceinline__ void grid_barrier(int idx, unsigned target)
{
    __threadfence();
    __syncthreads();
    if (threadIdx.x == 0) {
        unsigned s = g_sense[idx];
        unsigned arrived = atomicAdd(&g_count[idx], 1u);
        if (arrived == target - 1u) {
            g_count[idx] = 0u;
            __threadfence();
            g_sense[idx] = s + 1u;
        } else {
            while (g_sense[idx] == s) { }
        }
    }
    __syncthreads();
}

// Arrive-only (no spin): for blocks that exit after contributing.
__device__ __forceinline__ void grid_barrier_arrive(int idx, unsigned target)
{
    __threadfence();
    __syncthreads();
    if (threadIdx.x == 0) {
        unsigned s = g_sense[idx];
        unsigned arrived = atomicAdd(&g_count[idx], 1u);
        if (arrived == target - 1u) {
            g_count[idx] = 0u;
            __threadfence();
            g_sense[idx] = s + 1u;
        }
    }
}

// smem (dynamic, aliased between phases):
// Phase A: pj4 (500 float4) | dataS 500*65 | corrS 64 | cnt        (~138 KB)
// Phase B: xs 64*264 | ws 32*264 | dotS 2048 | mS 32 | iS 32       (~110 KB)
#define SMEM_FLOATS (4 * NN + NN * 65 + 64 + 8)
#define SMEM_BYTES  (SMEM_FLOATS * 4)

__global__ __launch_bounds__(THREADS, 1)
void mega_kernel(const float* __restrict__ xyz,   // [B,3,N]
                 const float* __restrict__ pts,   // [B,C,N]
                 const float* __restrict__ l3,    // [B,C]
                 const float* __restrict__ temp,  // [B,1,N]
                 const float* __restrict__ w0, const float* __restrict__ b0,
                 const float* __restrict__ g0, const float* __restrict__ e0,
                 const float* __restrict__ w1, const float* __restrict__ b1,
                 const float* __restrict__ g1, const float* __restrict__ e1,
                 const float* __restrict__ w2, const float* __restrict__ b2,
                 const float* __restrict__ g2, const float* __restrict__ e2,
                 const float* __restrict__ w3, const float* __restrict__ b3,
                 const float* __restrict__ g3, const float* __restrict__ e3,
                 const float* __restrict__ w4, const float* __restrict__ b4,
                 float* __restrict__ tc,
                 float* __restrict__ tsys,
                 float* __restrict__ opts,
                 float* __restrict__ ocorr)
{
    extern __shared__ float sm[];
    const int tid  = threadIdx.x;
    const int bid  = blockIdx.x;
    const int warp = tid >> 5;
    const int lane = tid & 31;

    const int b    = bid >> 1;
    const int half = bid & 1;

    // ------------------------------------------------------------------
    // Phase A0: tsys (odd blocks)
    // ------------------------------------------------------------------
    if (half == 1) {
        float s = (tid < NN) ? temp[b * NN + tid] : 0.0f;
        #pragma unroll
        for (int off = 16; off; off >>= 1) s += __shfl_down_sync(0xffffffffu, s, off);
        if (lane == 0) sm[warp] = s;
        __syncthreads();
        if (tid < 32) {
            float v = (tid < 16) ? sm[tid] : 0.0f;
            #pragma unroll
            for (int off = 8; off; off >>= 1) v += __shfl_down_sync(0xffffffffu, v, off);
            if (tid == 0) tsys[b] = v * (1.0f / (float)NN);
        }
        __syncthreads();
    }

    // ------------------------------------------------------------------
    // Phase A1: l2_points passthrough copy (streaming)
    // ------------------------------------------------------------------
    {
        const float4* s4 = (const float4*)pts;
        float4*       d4 = (float4*)opts;
        const int total4 = (BB * CC * NN) / 4;
        #pragma unroll 2
        for (int i = bid * THREADS + tid; i < total4; i += GRIDN * THREADS)
            __stcs(d4 + i, __ldcs(s4 + i));
    }

    // ------------------------------------------------------------------
    // Phase A2: correlation (R8 structure, unchanged)
    // ------------------------------------------------------------------
    {
        float4* pj4   = (float4*)sm;           // 500 x {x,y,z,s}
        float*  dataS = sm + 4 * NN;           // NN * 65
        float*  corrS = dataS + NN * 65;       // 64
        int*    cntS  = (int*)(corrS + 64);

        if (tid < 64) corrS[tid] = 0.0f;
        if (tid == 64) *cntS = 0;

        const float* xb = xyz + (size_t)b * 3 * NN;
        for (int i = tid; i < NN; i += THREADS) {
            float x = xb[i];
            float y = xb[NN + i];
            float z = xb[2 * NN + i];
            pj4[i] = make_float4(x, y, z, x * x + y * y + z * z);
        }

        const float* pb = pts + (size_t)b * CC * NN + (size_t)half * 64 * NN;
        for (int idx = tid; idx < 64 * NN; idx += THREADS) {
            int c = idx / NN;
            int j = idx - c * NN;
            dataS[j * 65 + c] = pb[c * NN + j];
        }
        __syncthreads();

        float corr0 = 0.0f, corr1 = 0.0f;
        int   cnt   = 0;

        for (int i = warp; i < NN; i += 32) {
            const float4 pi = pj4[i];
            const float di0 = dataS[i * 65 + lane];
            const float di1 = dataS[i * 65 + 32 + lane];
            float t0 = 0.0f, t1 = 0.0f;

            const int jb0 = i & ~31;

            // diagonal block
            {
                const int j = jb0 + lane;
                bool pred = false;
                if (j > i && j < NN) {
                    float4 pj = pj4[j];
                    float dot = pi.x * pj.x + pi.y * pj.y + pi.z * pj.z;
                    float sq  = fabsf(pi.w + pj.w - 2.0f * dot);
                    pred = (sq > LO2) && (sq < HI2);
                }
                unsigned m = __ballot_sync(0xffffffffu, pred);
                cnt += __popc(m);
                while (m) {
                    int jj = jb0 + (__ffs(m) - 1);
                    m &= m - 1;
                    t0 += dataS[jj * 65 + lane];
                    t1 += dataS[jj * 65 + 32 + lane];
                }
            }

            // full blocks
            #pragma unroll 2
            for (int jb = jb0 + 32; jb < 480; jb += 32) {
                float4 pj = pj4[jb + lane];
                float dot = pi.x * pj.x + pi.y * pj.y + pi.z * pj.z;
                float sq  = fabsf(pi.w + pj.w - 2.0f * dot);
                bool pred = (sq > LO2) && (sq < HI2);
                unsigned m = __ballot_sync(0xffffffffu, pred);
                cnt += __popc(m);
                while (m) {
                    int jj = jb + (__ffs(m) - 1);
                    m &= m - 1;
                    t0 += dataS[jj * 65 + lane];
                    t1 += dataS[jj * 65 + 32 + lane];
                }
            }

            // tail block
            if (jb0 < 480) {
                const int j = 480 + lane;
                bool pred = false;
                if (j < NN) {
                    float4 pj = pj4[j];
                    float dot = pi.x * pj.x + pi.y * pj.y + pi.z * pj.z;
                    float sq  = fabsf(pi.w + pj.w - 2.0f * dot);
                    pred = (sq > LO2) && (sq < HI2);
                }
                unsigned m = __ballot_sync(0xffffffffu, pred);
                cnt += __popc(m);
                while (m) {
                    int jj = 480 + (__ffs(m) - 1);
                    m &= m - 1;
                    t0 += dataS[jj * 65 + lane];
                    t1 += dataS[jj * 65 + 32 + lane];
                }
            }

            corr0 += t0 * di0;
            corr1 += t1 * di1;
        }

        atomicAdd(&corrS[lane],      corr0);
        atomicAdd(&corrS[32 + lane], corr1);
        if (lane == 0) atomicAdd(cntS, cnt);
        __syncthreads();

        if (tid < 64) {
            float cf = fmaxf((float)(*cntS), 1.0f);
            ocorr[b * CC + half * 64 + tid] = corrS[tid] / cf;
        }
    }

    // Barrier 0: all 128 blocks arrive; only blocks 0..7 continue.
    if (bid >= GRIDB) {
        grid_barrier_arrive(0, GRIDN);
        return;
    }
    grid_barrier(0, GRIDN);

    // ------------------------------------------------------------------
    // Phase B: 4 BN-MLP layers on GRIDB=8 blocks; 32 output columns each.
    // ------------------------------------------------------------------
    {
        float* xs   = sm;                        // 64 * XS_STRIDE
        float* ws   = xs + BB * XS_STRIDE;       // 32 * XS_STRIDE
        float* dotS = ws + 32 * XS_STRIDE;       // 2048 : dotS[oc*64 + n]
        float* mS   = dotS + 2048;               // 32
        float* iS   = mS + 32;                   // 32

        const float* Wl[4] = {w0, w1, w2, w3};
        const float* Bl[4] = {b0, b1, b2, b3};
        const float* Gl[4] = {g0, g1, g2, g3};
        const float* El[4] = {e0, e1, e2, e3};

        const int o0 = bid * 32;

        for (int l = 0; l < 4; l++) {
            // --- load x [64,256] into smem (padded stride), float4 ---
            if (l == 0) {
                const float4* c4p = (const float4*)ocorr;
                const float4* l4p = (const float4*)l3;
                for (int i = tid; i < BB * 64; i += THREADS) {
                    int n = i >> 6, c4 = i & 63;
                    float4 v = (c4 < 32) ? __ldcg(c4p + n * 32 + c4)
                                         : __ldcg(l4p + n * 32 + (c4 - 32));
                    *(float4*)&xs[n * XS_STRIDE + c4 * 4] = v;
                }
            } else {
                const float4* src = (const float4*)&g_act[(l + 1) & 1][0];
                for (int i = tid; i < BB * 64; i += THREADS) {
                    int n = i >> 6, c4 = i & 63;
                    *(float4*)&xs[n * XS_STRIDE + c4 * 4] = __ldcg(src + i);
                }
            }
            // --- load 32 weight rows (float4, coalesced) ---
            {
                const float4* w4p = (const float4*)(Wl[l] + (size_t)o0 * HH);
                for (int i = tid; i < 32 * 64; i += THREADS) {
                    int oo = i >> 6, k4 = i & 63;
                    *(float4*)&ws[oo * XS_STRIDE + k4 * 4] = w4p[i];
                }
            }
            __syncthreads();

            // --- dots: 2048 dots x 8-way split-k = 16384 tasks, 16/thread ---
            #pragma unroll
            for (int pass = 0; pass < 16; pass++) {
                int gidx = pass * THREADS + tid;
                int sub  = gidx & 7;
                int outi = gidx >> 3;          // 0..2047
                int n    = outi & 63;
                int oc   = outi >> 6;          // 0..31
                const float* xr = &xs[n * XS_STRIDE + sub * 4];
                const float* wr = &ws[oc * XS_STRIDE + sub * 4];
                float p = 0.0f;
                #pragma unroll
                for (int t = 0; t < 8; t++) {
                    float4 xv = *(const float4*)(xr + t * 32);
                    float4 wv = *(const float4*)(wr + t * 32);
                    p = fmaf(xv.x, wv.x, p);
                    p = fmaf(xv.y, wv.y, p);
                    p = fmaf(xv.z, wv.z, p);
                    p = fmaf(xv.w, wv.w, p);
                }
                p += __shfl_down_sync(0xffffffffu, p, 4, 8);
                p += __shfl_down_sync(0xffffffffu, p, 2, 8);
                p += __shfl_down_sync(0xffffffffu, p, 1, 8);
                if (sub == 0) dotS[oc * 64 + n] = p + Bl[l][o0 + oc];
            }
            __syncthreads();

            // --- BN stats: warp w -> column w; conflict-free dotS reads ---
            if (warp < 32) {
                float a = dotS[warp * 64 + lane];
                float c = dotS[warp * 64 + lane + 32];
                float s = a + c, q = a * a + c * c;
                #pragma unroll
                for (int off = 16; off; off >>= 1) {
                    s += __shfl_down_sync(0xffffffffu, s, off);
                    q += __shfl_down_sync(0xffffffffu, q, off);
                }
                if (lane == 0) {
                    float m = s * (1.0f / 64.0f);
                    float v = q * (1.0f / 64.0f) - m * m;
                    mS[warp] = m;
                    iS[warp] = rsqrtf(v + 1e-5f);
                }
            }
            __syncthreads();

            // --- BN + relu, write ping-pong: 2048 vals, 2/thread ---
            for (int i = tid; i < 2048; i += THREADS) {
                int oc = i >> 6, n = i & 63;
                int o  = o0 + oc;
                float d = dotS[i];
                float h = Gl[l][o] * (d - mS[oc]) * iS[oc] + El[l][o];
                g_act[l & 1][n * HH + o] = fmaxf(h, 0.0f);
            }

            grid_barrier(1 + l, GRIDB);
        }
    }

    // ------------------------------------------------------------------
    // Final FC (block 0)
    // ------------------------------------------------------------------
    if (bid == 0) {
        const int n   = tid >> 4;
        const int sub = tid & 15;
        const float* hr = &g_act[1][n * HH + sub * 16];
        float p = 0.0f;
        #pragma unroll
        for (int t = 0; t < 16; t++)
            p = fmaf(__ldcg(hr + t), w4[sub * 16 + t], p);
        p += __shfl_down_sync(0xffffffffu, p, 8, 16);
        p += __shfl_down_sync(0xffffffffu, p, 4, 16);
        p += __shfl_down_sync(0xffffffffu, p, 2, 16);
        p += __shfl_down_sync(0xffffffffu, p, 1, 16);
        if (sub == 0) tc[n] = p + b4[0];
    }
}

// ---------------------------------------------------------------------------
extern "C" void kernel_launch(void* const* d_in, const int* in_sizes, int n_in,
                              void* d_out, int out_size)
{
    const float* xyz  = (const float*)d_in[0];
    const float* pts  = (const float*)d_in[1];
    const float* l3   = (const float*)d_in[2];
    const float* temp = (const float*)d_in[3];
    const float* w0   = (const float*)d_in[4];
    const float* b0   = (const float*)d_in[5];
    const float* g0   = (const float*)d_in[6];
    const float* e0   = (const float*)d_in[7];
    const float* w1   = (const float*)d_in[8];
    const float* b1   = (const float*)d_in[9];
    const float* g1   = (const float*)d_in[10];
    const float* e1   = (const float*)d_in[11];
    const float* w2   = (const float*)d_in[12];
    const float* b2   = (const float*)d_in[13];
    const float* g2   = (const float*)d_in[14];
    const float* e2   = (const float*)d_in[15];
    const float* w3   = (const float*)d_in[16];
    const float* b3   = (const float*)d_in[17];
    const float* g3   = (const float*)d_in[18];
    const float* e3   = (const float*)d_in[19];
    const float* w4   = (const float*)d_in[20];
    const float* b4   = (const float*)d_in[21];

    float* out   = (float*)d_out;
    float* tc    = out;
    float* tsys  = out + 64;
    float* opts  = out + 128;
    float* ocorr = out + 128 + (size_t)BB * CC * NN;

    cudaFuncSetAttribute(mega_kernel, cudaFuncAttributeMaxDynamicSharedMemorySize,
                         SMEM_BYTES);

    mega_kernel<<<GRIDN, THREADS, SMEM_BYTES>>>(
        xyz, pts, l3, temp,
        w0, b0, g0, e0,
        w1, b1, g1, e1,
        w2, b2, g2, e2,
        w3, b3, g3, e3,
        w4, b4,
        tc, tsys, opts, ocorr);

    (void)in_sizes; (void)n_in; (void)out_size;
}

// round 13
// speedup vs baseline: 1.7017x; 1.7017x over previous
#include <cuda_runtime.h>
#include <cstdint>

#define BB 64
#define NN 500
#define CC 128
#define HH 256
#define GRIDN 128
#define THREADS 1024
#define XS_STRIDE 264    // 256 + 8 pad

// band thresholds squared (0.19^2, 0.21^2)
#define LO2 0.0361f
#define HI2 0.0441f

// MLP activation ping-pong
__device__ __align__(16) float g_act[2][BB * HH];

// Phase A smem: pj4 (500 float4) | dataS 500*65 | corrS 64 | cnt  (~138 KB)
#define A_SMEM_FLOATS (4 * NN + NN * 65 + 64 + 8)
#define A_SMEM_BYTES  (A_SMEM_FLOATS * 4)

// MLP smem: xs 64*264 | ws 2*264 | dotS 128 | mS 2 | iS 2  (~70 KB)
#define MLP_SMEM_FLOATS (BB * XS_STRIDE + 2 * XS_STRIDE + 128 + 4)
#define MLP_SMEM_BYTES  (MLP_SMEM_FLOATS * 4)

// ---------------------------------------------------------------------------
// K1: Phase A — tsys + passthrough copy + correlation (R8 structure, verbatim)
// grid (128), 1024 threads; block = (b, channel-half)
// ---------------------------------------------------------------------------
__global__ __launch_bounds__(THREADS, 1)
void phaseA_kernel(const float* __restrict__ xyz,   // [B,3,N]
                   const float* __restrict__ pts,   // [B,C,N]
                   const float* __restrict__ temp,  // [B,1,N]
                   float* __restrict__ tsys,
                   float* __restrict__ opts,
                   float* __restrict__ ocorr)
{
    extern __shared__ float sm[];
    const int tid  = threadIdx.x;
    const int bid  = blockIdx.x;
    const int warp = tid >> 5;
    const int lane = tid & 31;

    const int b    = bid >> 1;
    const int half = bid & 1;

    // tsys (odd blocks)
    if (half == 1) {
        float s = (tid < NN) ? temp[b * NN + tid] : 0.0f;
        #pragma unroll
        for (int off = 16; off; off >>= 1) s += __shfl_down_sync(0xffffffffu, s, off);
        if (lane == 0) sm[warp] = s;
        __syncthreads();
        if (tid < 32) {
            float v = (tid < 16) ? sm[tid] : 0.0f;
            #pragma unroll
            for (int off = 8; off; off >>= 1) v += __shfl_down_sync(0xffffffffu, v, off);
            if (tid == 0) tsys[b] = v * (1.0f / (float)NN);
        }
        __syncthreads();
    }

    // passthrough copy (streaming)
    {
        const float4* s4 = (const float4*)pts;
        float4*       d4 = (float4*)opts;
        const int total4 = (BB * CC * NN) / 4;
        #pragma unroll 2
        for (int i = bid * THREADS + tid; i < total4; i += GRIDN * THREADS)
            __stcs(d4 + i, __ldcs(s4 + i));
    }

    // correlation
    {
        float4* pj4   = (float4*)sm;           // 500 x {x,y,z,s}
        float*  dataS = sm + 4 * NN;           // NN * 65
        float*  corrS = dataS + NN * 65;       // 64
        int*    cntS  = (int*)(corrS + 64);

        if (tid < 64) corrS[tid] = 0.0f;
        if (tid == 64) *cntS = 0;

        const float* xb = xyz + (size_t)b * 3 * NN;
        for (int i = tid; i < NN; i += THREADS) {
            float x = xb[i];
            float y = xb[NN + i];
            float z = xb[2 * NN + i];
            pj4[i] = make_float4(x, y, z, x * x + y * y + z * z);
        }

        const float* pb = pts + (size_t)b * CC * NN + (size_t)half * 64 * NN;
        for (int idx = tid; idx < 64 * NN; idx += THREADS) {
            int c = idx / NN;
            int j = idx - c * NN;
            dataS[j * 65 + c] = pb[c * NN + j];
        }
        __syncthreads();

        float corr0 = 0.0f, corr1 = 0.0f;
        int   cnt   = 0;

        for (int i = warp; i < NN; i += 32) {
            const float4 pi = pj4[i];
            const float di0 = dataS[i * 65 + lane];
            const float di1 = dataS[i * 65 + 32 + lane];
            float t0 = 0.0f, t1 = 0.0f;

            const int jb0 = i & ~31;

            // diagonal block
            {
                const int j = jb0 + lane;
                bool pred = false;
                if (j > i && j < NN) {
                    float4 pj = pj4[j];
                    float dot = pi.x * pj.x + pi.y * pj.y + pi.z * pj.z;
                    float sq  = fabsf(pi.w + pj.w - 2.0f * dot);
                    pred = (sq > LO2) && (sq < HI2);
                }
                unsigned m = __ballot_sync(0xffffffffu, pred);
                cnt += __popc(m);
                while (m) {
                    int jj = jb0 + (__ffs(m) - 1);
                    m &= m - 1;
                    t0 += dataS[jj * 65 + lane];
                    t1 += dataS[jj * 65 + 32 + lane];
                }
            }

            // full blocks
            #pragma unroll 2
            for (int jb = jb0 + 32; jb < 480; jb += 32) {
                float4 pj = pj4[jb + lane];
                float dot = pi.x * pj.x + pi.y * pj.y + pi.z * pj.z;
                float sq  = fabsf(pi.w + pj.w - 2.0f * dot);
                bool pred = (sq > LO2) && (sq < HI2);
                unsigned m = __ballot_sync(0xffffffffu, pred);
                cnt += __popc(m);
                while (m) {
                    int jj = jb + (__ffs(m) - 1);
                    m &= m - 1;
                    t0 += dataS[jj * 65 + lane];
                    t1 += dataS[jj * 65 + 32 + lane];
                }
            }

            // tail block
            if (jb0 < 480) {
                const int j = 480 + lane;
                bool pred = false;
                if (j < NN) {
                    float4 pj = pj4[j];
                    float dot = pi.x * pj.x + pi.y * pj.y + pi.z * pj.z;
                    float sq  = fabsf(pi.w + pj.w - 2.0f * dot);
                    pred = (sq > LO2) && (sq < HI2);
                }
                unsigned m = __ballot_sync(0xffffffffu, pred);
                cnt += __popc(m);
                while (m) {
                    int jj = 480 + (__ffs(m) - 1);
                    m &= m - 1;
                    t0 += dataS[jj * 65 + lane];
                    t1 += dataS[jj * 65 + 32 + lane];
                }
            }

            corr0 += t0 * di0;
            corr1 += t1 * di1;
        }

        atomicAdd(&corrS[lane],      corr0);
        atomicAdd(&corrS[32 + lane], corr1);
        if (lane == 0) atomicAdd(cntS, cnt);
        __syncthreads();

        if (tid < 64) {
            float cf = fmaxf((float)(*cntS), 1.0f);
            ocorr[b * CC + half * 64 + tid] = corrS[tid] / cf;
        }
    }
}

// ---------------------------------------------------------------------------
// MLP layer kernel: 128 blocks x 256 threads, 2 output columns per block.
// Same per-block structure as R8's Phase B (measured fast); graph edge
// replaces the software grid barrier.
// ---------------------------------------------------------------------------
__global__ __launch_bounds__(256, 1)
void mlp_layer(const float* __restrict__ x0,
               const float* __restrict__ x1, int split,
               const float* __restrict__ W,
               const float* __restrict__ bias,
               const float* __restrict__ gam,
               const float* __restrict__ bet,
               float* __restrict__ out)
{
    extern __shared__ float sm[];
    float* xs   = sm;                       // 64 * XS_STRIDE
    float* ws   = xs + BB * XS_STRIDE;      // 2 * XS_STRIDE
    float* dotS = ws + 2 * XS_STRIDE;       // 128
    float* mS   = dotS + 128;               // 2
    float* iS   = mS + 2;                   // 2

    const int tid = threadIdx.x;
    const int o0  = blockIdx.x * 2;

    // load x [64,256] into smem (padded stride), float4
    if (split) {
        const float4* c4p = (const float4*)x0;   // corr [B,128]
        const float4* l4p = (const float4*)x1;   // l3   [B,128]
        for (int i = tid; i < BB * 64; i += 256) {
            int n = i >> 6, c4 = i & 63;
            float4 v = (c4 < 32) ? c4p[n * 32 + c4] : l4p[n * 32 + (c4 - 32)];
            *(float4*)&xs[n * XS_STRIDE + c4 * 4] = v;
        }
    } else {
        const float4* src = (const float4*)x0;
        for (int i = tid; i < BB * 64; i += 256) {
            int n = i >> 6, c4 = i & 63;
            *(float4*)&xs[n * XS_STRIDE + c4 * 4] = src[i];
        }
    }
    // load this block's 2 weight rows (128 float4)
    if (tid < 128) {
        const float4* w4p = (const float4*)(W + (size_t)o0 * HH);
        int oo = tid >> 6, k4 = tid & 63;
        *(float4*)&ws[oo * XS_STRIDE + k4 * 4] = w4p[tid];
    }
    __syncthreads();

    // dots: 128 outputs x 8-way split-k = 1024 tasks, 4 per thread
    #pragma unroll
    for (int pass = 0; pass < 4; pass++) {
        int gidx = pass * 256 + tid;
        int sub  = gidx & 7;
        int outi = gidx >> 3;          // 0..127
        int n    = outi >> 1;
        int oc   = outi & 1;
        const float* xr = &xs[n * XS_STRIDE + sub * 4];
        const float* wr = &ws[oc * XS_STRIDE + sub * 4];
        float p = 0.0f;
        #pragma unroll
        for (int t = 0; t < 8; t++) {
            float4 xv = *(const float4*)(xr + t * 32);
            float4 wv = *(const float4*)(wr + t * 32);
            p = fmaf(xv.x, wv.x, p);
            p = fmaf(xv.y, wv.y, p);
            p = fmaf(xv.z, wv.z, p);
            p = fmaf(xv.w, wv.w, p);
        }
        p += __shfl_down_sync(0xffffffffu, p, 4, 8);
        p += __shfl_down_sync(0xffffffffu, p, 2, 8);
        p += __shfl_down_sync(0xffffffffu, p, 1, 8);
        if (sub == 0) dotS[outi] = p + bias[o0 + oc];
    }
    __syncthreads();

    // BN stats per column
    if (tid < 64) {
        int oc2 = tid >> 5;
        int ll  = tid & 31;
        float a = dotS[ll * 2 + oc2];
        float c = dotS[(ll + 32) * 2 + oc2];
        float s = a + c, q = a * a + c * c;
        #pragma unroll
        for (int off = 16; off; off >>= 1) {
            s += __shfl_down_sync(0xffffffffu, s, off);
            q += __shfl_down_sync(0xffffffffu, q, off);
        }
        if (ll == 0) {
            float m = s * (1.0f / 64.0f);
            float v = q * (1.0f / 64.0f) - m * m;
            mS[oc2] = m;
            iS[oc2] = rsqrtf(v + 1e-5f);
        }
    }
    __syncthreads();

    // BN + relu, write
    if (tid < 128) {
        int nn = tid >> 1, occ = tid & 1;
        int o  = o0 + occ;
        float d = dotS[tid];
        float h = gam[o] * (d - mS[occ]) * iS[occ] + bet[o];
        out[nn * HH + o] = fmaxf(h, 0.0f);
    }
}

// ---------------------------------------------------------------------------
// Final FC: tc[n] = h[n,:] . w4 + b4   (1 block, 1024 threads)
// ---------------------------------------------------------------------------
__global__ __launch_bounds__(THREADS, 1)
void fc_final(const float* __restrict__ h,
              const float* __restrict__ w4,
              const float* __restrict__ b4,
              float* __restrict__ tc)
{
    const int tid = threadIdx.x;
    const int n   = tid >> 4;
    const int sub = tid & 15;
    const float* hr = &h[n * HH + sub * 16];
    float p = 0.0f;
    #pragma unroll
    for (int t = 0; t < 16; t++)
        p = fmaf(hr[t], w4[sub * 16 + t], p);
    p += __shfl_down_sync(0xffffffffu, p, 8, 16);
    p += __shfl_down_sync(0xffffffffu, p, 4, 16);
    p += __shfl_down_sync(0xffffffffu, p, 2, 16);
    p += __shfl_down_sync(0xffffffffu, p, 1, 16);
    if (sub == 0) tc[n] = p + b4[0];
}

// ---------------------------------------------------------------------------
extern "C" void kernel_launch(void* const* d_in, const int* in_sizes, int n_in,
                              void* d_out, int out_size)
{
    const float* xyz  = (const float*)d_in[0];
    const float* pts  = (const float*)d_in[1];
    const float* l3   = (const float*)d_in[2];
    const float* temp = (const float*)d_in[3];
    const float* w0   = (const float*)d_in[4];
    const float* b0   = (const float*)d_in[5];
    const float* g0   = (const float*)d_in[6];
    const float* e0   = (const float*)d_in[7];
    const float* w1   = (const float*)d_in[8];
    const float* b1   = (const float*)d_in[9];
    const float* g1   = (const float*)d_in[10];
    const float* e1   = (const float*)d_in[11];
    const float* w2   = (const float*)d_in[12];
    const float* b2   = (const float*)d_in[13];
    const float* g2   = (const float*)d_in[14];
    const float* e2   = (const float*)d_in[15];
    const float* w3   = (const float*)d_in[16];
    const float* b3   = (const float*)d_in[17];
    const float* g3   = (const float*)d_in[18];
    const float* e3   = (const float*)d_in[19];
    const float* w4   = (const float*)d_in[20];
    const float* b4   = (const float*)d_in[21];

    float* out   = (float*)d_out;
    float* tc    = out;
    float* tsys  = out + 64;
    float* opts  = out + 128;
    float* ocorr = out + 128 + (size_t)BB * CC * NN;

    cudaFuncSetAttribute(phaseA_kernel, cudaFuncAttributeMaxDynamicSharedMemorySize,
                         A_SMEM_BYTES);
    cudaFuncSetAttribute(mlp_layer, cudaFuncAttributeMaxDynamicSharedMemorySize,
                         MLP_SMEM_BYTES);

    float* act0 = nullptr;
    cudaGetSymbolAddress((void**)&act0, g_act);
    float* act1 = act0 + BB * HH;

    phaseA_kernel<<<GRIDN, THREADS, A_SMEM_BYTES>>>(xyz, pts, temp,
                                                    tsys, opts, ocorr);

    mlp_layer<<<GRIDN, 256, MLP_SMEM_BYTES>>>(ocorr, l3, 1, w0, b0, g0, e0, act0);
    mlp_layer<<<GRIDN, 256, MLP_SMEM_BYTES>>>(act0, nullptr, 0, w1, b1, g1, e1, act1);
    mlp_layer<<<GRIDN, 256, MLP_SMEM_BYTES>>>(act1, nullptr, 0, w2, b2, g2, e2, act0);
    mlp_layer<<<GRIDN, 256, MLP_SMEM_BYTES>>>(act0, nullptr, 0, w3, b3, g3, e3, act1);
    fc_final<<<1, THREADS>>>(act1, w4, b4, tc);

    (void)in_sizes; (void)n_in; (void)out_size;
}

// round 15
// speedup vs baseline: 1.9510x; 1.1465x over previous
#include <cuda_runtime.h>
#include <cstdint>

#define BB 64
#define NN 500
#define CC 128
#define HH 256
#define GRIDN 128
#define THREADS 1024
#define XS_STRIDE 264    // 256 + 8 pad

// band thresholds squared (0.19^2, 0.21^2)
#define LO2 0.0361f
#define HI2 0.0441f

// MLP activation ping-pong
__device__ __align__(16) float g_act[2][BB * HH];

// Two-level barrier state. Leaves padded to 128B (32 u32) so the 8 leaf
// counters live on different L2 slices; root + sense padded likewise.
#define NLEAF 8
#define LEAFSZ (GRIDN / NLEAF)      // 16
__device__ unsigned g_leaf[8][NLEAF * 32];   // barrier idx x leaf*32
__device__ unsigned g_root[8 * 32];
__device__ volatile unsigned g_sense[8 * 32];

// Two-level tree barrier with nanosleep-backoff spin.
// Arrival: leaf atomic (16 contenders) -> root atomic (8 contenders).
// Spin: sense poll with __nanosleep backoff (no LTS poll storm).
__device__ __forceinline__ void grid_barrier(int idx)
{
    __threadfence();
    __syncthreads();
    if (threadIdx.x == 0) {
        unsigned s = g_sense[idx * 32];
        int leaf = blockIdx.x & (NLEAF - 1);
        if (atomicAdd(&g_leaf[idx][leaf * 32], 1u) == LEAFSZ - 1u) {
            g_leaf[idx][leaf * 32] = 0u;
            if (atomicAdd(&g_root[idx * 32], 1u) == NLEAF - 1u) {
                g_root[idx * 32] = 0u;
                __threadfence();
                g_sense[idx * 32] = s + 1u;
            }
        }
        while (g_sense[idx * 32] == s) __nanosleep(100);
    }
    __syncthreads();
}

// Arrive-only variant (no spin) for blocks that exit afterwards.
__device__ __forceinline__ void grid_barrier_arrive(int idx)
{
    __threadfence();
    __syncthreads();
    if (threadIdx.x == 0) {
        unsigned s = g_sense[idx * 32];
        int leaf = blockIdx.x & (NLEAF - 1);
        if (atomicAdd(&g_leaf[idx][leaf * 32], 1u) == LEAFSZ - 1u) {
            g_leaf[idx][leaf * 32] = 0u;
            if (atomicAdd(&g_root[idx * 32], 1u) == NLEAF - 1u) {
                g_root[idx * 32] = 0u;
                __threadfence();
                g_sense[idx * 32] = s + 1u;
            }
        }
    }
}

// smem (dynamic, aliased between phases):
// Phase A: pj4 (500 float4) | dataS 500*65 | corrS 64 | cnt
// Phase B: xs 64*264 | ws 2*264 | dotS 128 | mS 2 | iS 2
#define SMEM_FLOATS (4 * NN + NN * 65 + 64 + 8)
#define SMEM_BYTES  (SMEM_FLOATS * 4)

__global__ __launch_bounds__(THREADS, 1)
void mega_kernel(const float* __restrict__ xyz,   // [B,3,N]
                 const float* __restrict__ pts,   // [B,C,N]
                 const float* __restrict__ l3,    // [B,C]
                 const float* __restrict__ temp,  // [B,1,N]
                 const float* __restrict__ w0, const float* __restrict__ b0,
                 const float* __restrict__ g0, const float* __restrict__ e0,
                 const float* __restrict__ w1, const float* __restrict__ b1,
                 const float* __restrict__ g1, const float* __restrict__ e1,
                 const float* __restrict__ w2, const float* __restrict__ b2,
                 const float* __restrict__ g2, const float* __restrict__ e2,
                 const float* __restrict__ w3, const float* __restrict__ b3,
                 const float* __restrict__ g3, const float* __restrict__ e3,
                 const float* __restrict__ w4, const float* __restrict__ b4,
                 float* __restrict__ tc,
                 float* __restrict__ tsys,
                 float* __restrict__ opts,
                 float* __restrict__ ocorr)
{
    extern __shared__ float sm[];
    const int tid  = threadIdx.x;
    const int bid  = blockIdx.x;
    const int warp = tid >> 5;
    const int lane = tid & 31;

    const int b    = bid >> 1;
    const int half = bid & 1;

    // ------------------------------------------------------------------
    // Phase A0: tsys (odd blocks)
    // ------------------------------------------------------------------
    if (half == 1) {
        float s = (tid < NN) ? temp[b * NN + tid] : 0.0f;
        #pragma unroll
        for (int off = 16; off; off >>= 1) s += __shfl_down_sync(0xffffffffu, s, off);
        if (lane == 0) sm[warp] = s;
        __syncthreads();
        if (tid < 32) {
            float v = (tid < 16) ? sm[tid] : 0.0f;
            #pragma unroll
            for (int off = 8; off; off >>= 1) v += __shfl_down_sync(0xffffffffu, v, off);
            if (tid == 0) tsys[b] = v * (1.0f / (float)NN);
        }
        __syncthreads();
    }

    // ------------------------------------------------------------------
    // Phase A1: l2_points passthrough copy (streaming)
    // ------------------------------------------------------------------
    {
        const float4* s4 = (const float4*)pts;
        float4*       d4 = (float4*)opts;
        const int total4 = (BB * CC * NN) / 4;
        #pragma unroll 2
        for (int i = bid * THREADS + tid; i < total4; i += GRIDN * THREADS)
            __stcs(d4 + i, __ldcs(s4 + i));
    }

    // ------------------------------------------------------------------
    // Phase A2: correlation (R8 structure, unchanged)
    // ------------------------------------------------------------------
    {
        float4* pj4   = (float4*)sm;           // 500 x {x,y,z,s}
        float*  dataS = sm + 4 * NN;           // NN * 65
        float*  corrS = dataS + NN * 65;       // 64
        int*    cntS  = (int*)(corrS + 64);

        if (tid < 64) corrS[tid] = 0.0f;
        if (tid == 64) *cntS = 0;

        const float* xb = xyz + (size_t)b * 3 * NN;
        for (int i = tid; i < NN; i += THREADS) {
            float x = xb[i];
            float y = xb[NN + i];
            float z = xb[2 * NN + i];
            pj4[i] = make_float4(x, y, z, x * x + y * y + z * z);
        }

        const float* pb = pts + (size_t)b * CC * NN + (size_t)half * 64 * NN;
        for (int idx = tid; idx < 64 * NN; idx += THREADS) {
            int c = idx / NN;
            int j = idx - c * NN;
            dataS[j * 65 + c] = pb[c * NN + j];
        }
        __syncthreads();

        float corr0 = 0.0f, corr1 = 0.0f;
        int   cnt   = 0;

        for (int i = warp; i < NN; i += 32) {
            const float4 pi = pj4[i];
            const float di0 = dataS[i * 65 + lane];
            const float di1 = dataS[i * 65 + 32 + lane];
            float t0 = 0.0f, t1 = 0.0f;

            const int jb0 = i & ~31;

            // diagonal block
            {
                const int j = jb0 + lane;
                bool pred = false;
                if (j > i && j < NN) {
                    float4 pj = pj4[j];
                    float dot = pi.x * pj.x + pi.y * pj.y + pi.z * pj.z;
                    float sq  = fabsf(pi.w + pj.w - 2.0f * dot);
                    pred = (sq > LO2) && (sq < HI2);
                }
                unsigned m = __ballot_sync(0xffffffffu, pred);
                cnt += __popc(m);
                while (m) {
                    int jj = jb0 + (__ffs(m) - 1);
                    m &= m - 1;
                    t0 += dataS[jj * 65 + lane];
                    t1 += dataS[jj * 65 + 32 + lane];
                }
            }

            // full blocks
            #pragma unroll 2
            for (int jb = jb0 + 32; jb < 480; jb += 32) {
                float4 pj = pj4[jb + lane];
                float dot = pi.x * pj.x + pi.y * pj.y + pi.z * pj.z;
                float sq  = fabsf(pi.w + pj.w - 2.0f * dot);
                bool pred = (sq > LO2) && (sq < HI2);
                unsigned m = __ballot_sync(0xffffffffu, pred);
                cnt += __popc(m);
                while (m) {
                    int jj = jb + (__ffs(m) - 1);
                    m &= m - 1;
                    t0 += dataS[jj * 65 + lane];
                    t1 += dataS[jj * 65 + 32 + lane];
                }
            }

            // tail block
            if (jb0 < 480) {
                const int j = 480 + lane;
                bool pred = false;
                if (j < NN) {
                    float4 pj = pj4[j];
                    float dot = pi.x * pj.x + pi.y * pj.y + pi.z * pj.z;
                    float sq  = fabsf(pi.w + pj.w - 2.0f * dot);
                    pred = (sq > LO2) && (sq < HI2);
                }
                unsigned m = __ballot_sync(0xffffffffu, pred);
                cnt += __popc(m);
                while (m) {
                    int jj = 480 + (__ffs(m) - 1);
                    m &= m - 1;
                    t0 += dataS[jj * 65 + lane];
                    t1 += dataS[jj * 65 + 32 + lane];
                }
            }

            corr0 += t0 * di0;
            corr1 += t1 * di1;
        }

        atomicAdd(&corrS[lane],      corr0);
        atomicAdd(&corrS[32 + lane], corr1);
        if (lane == 0) atomicAdd(cntS, cnt);
        __syncthreads();

        if (tid < 64) {
            float cf = fmaxf((float)(*cntS), 1.0f);
            ocorr[b * CC + half * 64 + tid] = corrS[tid] / cf;
        }
    }

    grid_barrier(0);

    // ------------------------------------------------------------------
    // Phase B: 4 BN-MLP layers. Each block owns 2 output columns. (R8)
    // ------------------------------------------------------------------
    {
        float* xs   = sm;                       // 64 * XS_STRIDE
        float* ws   = xs + BB * XS_STRIDE;      // 2 * XS_STRIDE
        float* dotS = ws + 2 * XS_STRIDE;       // 128
        float* mS   = dotS + 128;               // 2
        float* iS   = mS + 2;                   // 2

        const float* Wl[4] = {w0, w1, w2, w3};
        const float* Bl[4] = {b0, b1, b2, b3};
        const float* Gl[4] = {g0, g1, g2, g3};
        const float* El[4] = {e0, e1, e2, e3};

        const int o0 = bid * 2;

        for (int l = 0; l < 4; l++) {
            if (l == 0) {
                const float4* c4p = (const float4*)ocorr;
                const float4* l4p = (const float4*)l3;
                for (int i = tid; i < BB * 64; i += THREADS) {
                    int n = i >> 6, c4 = i & 63;
                    float4 v = (c4 < 32) ? __ldcg(c4p + n * 32 + c4)
                                         : __ldcg(l4p + n * 32 + (c4 - 32));
                    *(float4*)&xs[n * XS_STRIDE + c4 * 4] = v;
                }
            } else {
                const float4* src = (const float4*)&g_act[(l + 1) & 1][0];
                for (int i = tid; i < BB * 64; i += THREADS) {
                    int n = i >> 6, c4 = i & 63;
                    *(float4*)&xs[n * XS_STRIDE + c4 * 4] = __ldcg(src + i);
                }
            }
            if (tid < 2 * HH) {
                int oo = tid >> 8, k = tid & 255;
                ws[oo * XS_STRIDE + k] = Wl[l][(size_t)(o0 + oo) * HH + k];
            }
            __syncthreads();

            const int sub  = tid & 7;
            const int outi = tid >> 3;
            const int n    = outi >> 1;
            const int oc   = outi & 1;
            {
                const float* xr = &xs[n * XS_STRIDE + sub * 4];
                const float* wr = &ws[oc * XS_STRIDE + sub * 4];
                float p = 0.0f;
                #pragma unroll
                for (int t = 0; t < 8; t++) {
                    float4 xv = *(const float4*)(xr + t * 32);
                    float4 wv = *(const float4*)(wr + t * 32);
                    p = fmaf(xv.x, wv.x, p);
                    p = fmaf(xv.y, wv.y, p);
                    p = fmaf(xv.z, wv.z, p);
                    p = fmaf(xv.w, wv.w, p);
                }
                p += __shfl_down_sync(0xffffffffu, p, 4, 8);
                p += __shfl_down_sync(0xffffffffu, p, 2, 8);
                p += __shfl_down_sync(0xffffffffu, p, 1, 8);
                if (sub == 0) dotS[outi] = p + Bl[l][o0 + oc];
            }
            __syncthreads();

            if (tid < 64) {
                int oc2 = tid >> 5;
                int ll  = tid & 31;
                float a = dotS[ll * 2 + oc2];
                float c = dotS[(ll + 32) * 2 + oc2];
                float s = a + c, q = a * a + c * c;
                #pragma unroll
                for (int off = 16; off; off >>= 1) {
                    s += __shfl_down_sync(0xffffffffu, s, off);
                    q += __shfl_down_sync(0xffffffffu, q, off);
                }
                if (ll == 0) {
                    float m = s * (1.0f / 64.0f);
                    float v = q * (1.0f / 64.0f) - m * m;
                    mS[oc2] = m;
                    iS[oc2] = rsqrtf(v + 1e-5f);
                }
            }
            __syncthreads();

            if (tid < 128) {
                int nn = tid >> 1, occ = tid & 1;
                int o  = o0 + occ;
                float d = dotS[tid];
                float h = Gl[l][o] * (d - mS[occ]) * iS[occ] + El[l][o];
                g_act[l & 1][nn * HH + o] = fmaxf(h, 0.0f);
            }

            // Last layer: non-zero blocks arrive and exit; block 0 spins.
            if (l == 3 && bid != 0) {
                grid_barrier_arrive(4);
                return;
            }
            grid_barrier(1 + l);
        }
    }

    // ------------------------------------------------------------------
    // Final FC (block 0)
    // ------------------------------------------------------------------
    if (bid == 0) {
        const int n   = tid >> 4;
        const int sub = tid & 15;
        const float* hr = &g_act[1][n * HH + sub * 16];
        float p = 0.0f;
        #pragma unroll
        for (int t = 0; t < 16; t++)
            p = fmaf(__ldcg(hr + t), w4[sub * 16 + t], p);
        p += __shfl_down_sync(0xffffffffu, p, 8, 16);
        p += __shfl_down_sync(0xffffffffu, p, 4, 16);
        p += __shfl_down_sync(0xffffffffu, p, 2, 16);
        p += __shfl_down_sync(0xffffffffu, p, 1, 16);
        if (sub == 0) tc[n] = p + b4[0];
    }
}

// ---------------------------------------------------------------------------
extern "C" void kernel_launch(void* const* d_in, const int* in_sizes, int n_in,
                              void* d_out, int out_size)
{
    const float* xyz  = (const float*)d_in[0];
    const float* pts  = (const float*)d_in[1];
    const float* l3   = (const float*)d_in[2];
    const float* temp = (const float*)d_in[3];
    const float* w0   = (const float*)d_in[4];
    const float* b0   = (const float*)d_in[5];
    const float* g0   = (const float*)d_in[6];
    const float* e0   = (const float*)d_in[7];
    const float* w1   = (const float*)d_in[8];
    const float* b1   = (const float*)d_in[9];
    const float* g1   = (const float*)d_in[10];
    const float* e1   = (const float*)d_in[11];
    const float* w2   = (const float*)d_in[12];
    const float* b2   = (const float*)d_in[13];
    const float* g2   = (const float*)d_in[14];
    const float* e2   = (const float*)d_in[15];
    const float* w3   = (const float*)d_in[16];
    const float* b3   = (const float*)d_in[17];
    const float* g3   = (const float*)d_in[18];
    const float* e3   = (const float*)d_in[19];
    const float* w4   = (const float*)d_in[20];
    const float* b4   = (const float*)d_in[21];

    float* out   = (float*)d_out;
    float* tc    = out;
    float* tsys  = out + 64;
    float* opts  = out + 128;
    float* ocorr = out + 128 + (size_t)BB * CC * NN;

    cudaFuncSetAttribute(mega_kernel, cudaFuncAttributeMaxDynamicSharedMemorySize,
                         SMEM_BYTES);

    mega_kernel<<<GRIDN, THREADS, SMEM_BYTES>>>(
        xyz, pts, l3, temp,
        w0, b0, g0, e0,
        w1, b1, g1, e1,
        w2, b2, g2, e2,
        w3, b3, g3, e3,
        w4, b4,
        tc, tsys, opts, ocorr);

    (void)in_sizes; (void)n_in; (void)out_size;
}